// round 2
// baseline (speedup 1.0000x reference)
#include <cuda_runtime.h>
#include <cstdint>

#define U_CNT 100000
#define I_CNT 50000
#define DIM   64
#define N_CNT 150000
#define NNZ_E 1000000

// ---- device scratch (static; no runtime allocation) ----
__device__ int  g_rowptr_a[N_CNT + 1];   // doubles as count buffer, then exclusive scan
__device__ int  g_rowptr_r[N_CNT + 1];
__device__ int  g_cursor_a[N_CNT];       // scatter cursors (copy of rowptr)
__device__ int  g_cursor_r[N_CNT];
__device__ int2 g_sorted_a[NNZ_E];       // (col, val bits) grouped by row
__device__ int2 g_sorted_r[NNZ_E];

static __device__ __forceinline__ const float4* ego_row(
    const float* __restrict__ ue, const float* __restrict__ ie, int n) {
    return (n < U_CNT)
        ? reinterpret_cast<const float4*>(ue + (size_t)n * DIM)
        : reinterpret_cast<const float4*>(ie + (size_t)(n - U_CNT) * DIM);
}

// K0: zero the per-row counters (graph replays must start clean).
__global__ void lgcn_zero() {
    int i = blockIdx.x * blockDim.x + threadIdx.x;
    if (i < N_CNT) { g_rowptr_a[i] = 0; g_rowptr_r[i] = 0; }
}

// K1: histogram of row indices for both matrices.
__global__ void lgcn_hist(const int* __restrict__ a_rows,
                          const int* __restrict__ r_rows) {
    int i = blockIdx.x * blockDim.x + threadIdx.x;
    if (i < NNZ_E) {
        atomicAdd(&g_rowptr_a[__ldg(&a_rows[i])], 1);
        atomicAdd(&g_rowptr_r[__ldg(&r_rows[i])], 1);
    }
}

// K2: exclusive scan of 150K counts, in place. One block per matrix.
__global__ void lgcn_scan() {
    int* cnt = blockIdx.x ? g_rowptr_r : g_rowptr_a;
    int* cur = blockIdx.x ? g_cursor_r : g_cursor_a;
    const int T = 1024;
    int t = threadIdx.x;
    const int C = (N_CNT + T - 1) / T;          // 147
    int start = t * C;
    int end   = min(start + C, N_CNT);
    int s = 0;
    for (int i = start; i < end; i++) s += cnt[i];
    __shared__ int sums[T];
    sums[t] = s;
    __syncthreads();
    // Hillis–Steele inclusive scan
    for (int off = 1; off < T; off <<= 1) {
        int v = (t >= off) ? sums[t - off] : 0;
        __syncthreads();
        sums[t] += v;
        __syncthreads();
    }
    int run = (t == 0) ? 0 : sums[t - 1];       // exclusive prefix
    for (int i = start; i < end; i++) {
        int c = cnt[i];
        cnt[i] = run;
        cur[i] = run;
        run += c;
    }
    if (t == T - 1) cnt[N_CNT] = run;           // total = NNZ_E
}

// K3: scatter (col, val) into row-grouped order for both matrices.
__global__ void lgcn_scatter(const int*  __restrict__ a_rows,
                             const int*  __restrict__ a_cols,
                             const float* __restrict__ a_vals,
                             const int*  __restrict__ r_rows,
                             const int*  __restrict__ r_cols,
                             const float* __restrict__ r_vals) {
    int i = blockIdx.x * blockDim.x + threadIdx.x;
    if (i >= NNZ_E) return;
    {
        int row = __ldg(&a_rows[i]);
        int pos = atomicAdd(&g_cursor_a[row], 1);
        g_sorted_a[pos] = make_int2(__ldg(&a_cols[i]), __float_as_int(__ldg(&a_vals[i])));
    }
    {
        int row = __ldg(&r_rows[i]);
        int pos = atomicAdd(&g_cursor_r[row], 1);
        g_sorted_r[pos] = make_int2(__ldg(&r_cols[i]), __float_as_int(__ldg(&r_vals[i])));
    }
}

// K4: per-row gather SpMM for both matrices + full output emit.
// 16 threads per row, each owning 4 consecutive feature dims (float4).
// Writes every output byte exactly once; no atomics.
__global__ void lgcn_gather(const float* __restrict__ ue,
                            const float* __restrict__ ie,
                            float* __restrict__ out) {
    int idx = blockIdx.x * blockDim.x + threadIdx.x;
    if (idx >= N_CNT * 16) return;
    int n = idx >> 4;
    int q = idx & 15;

    float4 e = __ldg(&ego_row(ue, ie, n)[q]);

    float4 a = make_float4(0.f, 0.f, 0.f, 0.f);
    int s0 = __ldg(&g_rowptr_a[n]);
    int e0 = __ldg(&g_rowptr_a[n + 1]);
    for (int i = s0; i < e0; i++) {
        int2 cv = __ldg(&g_sorted_a[i]);
        float v = __int_as_float(cv.y);
        float4 x = __ldg(&ego_row(ue, ie, cv.x)[q]);
        a.x = fmaf(v, x.x, a.x);
        a.y = fmaf(v, x.y, a.y);
        a.z = fmaf(v, x.z, a.z);
        a.w = fmaf(v, x.w, a.w);
    }

    float4 r = make_float4(0.f, 0.f, 0.f, 0.f);
    int s1 = __ldg(&g_rowptr_r[n]);
    int e1 = __ldg(&g_rowptr_r[n + 1]);
    for (int i = s1; i < e1; i++) {
        int2 cv = __ldg(&g_sorted_r[i]);
        float v = __int_as_float(cv.y);
        float4 x = __ldg(&ego_row(ue, ie, cv.x)[q]);
        r.x = fmaf(v, x.x, r.x);
        r.y = fmaf(v, x.y, r.y);
        r.z = fmaf(v, x.z, r.z);
        r.w = fmaf(v, x.w, r.w);
    }

    // output layout
    size_t sbase = (size_t)N_CNT * DIM + (size_t)n * 4 * DIM;
    size_t pbase = sbase + (size_t)N_CNT * 4 * DIM;
    float4* s = reinterpret_cast<float4*>(out + sbase);
    float4* p = reinterpret_cast<float4*>(out + pbase);
    s[q]      = e;            // stacked slot 0
    s[16 + q] = a;            // slots 1..3 identical (loop never updates ego)
    s[32 + q] = a;
    s[48 + q] = a;
    p[q]      = e;            // path slot 0
    p[16 + q] = r;
    p[32 + q] = r;
    p[48 + q] = r;

    float4 m = make_float4((e.x + 3.f * a.x) * 0.25f,
                           (e.y + 3.f * a.y) * 0.25f,
                           (e.z + 3.f * a.z) * 0.25f,
                           (e.w + 3.f * a.w) * 0.25f);
    reinterpret_cast<float4*>(out)[(size_t)n * 16 + q] = m;
}

extern "C" void kernel_launch(void* const* d_in, const int* in_sizes, int n_in,
                              void* d_out, int out_size) {
    const float* ue     = (const float*)d_in[0];
    const float* ie     = (const float*)d_in[1];
    const int*   a_rows = (const int*)  d_in[2];
    const int*   a_cols = (const int*)  d_in[3];
    const float* a_vals = (const float*)d_in[4];
    const int*   r_rows = (const int*)  d_in[5];
    const int*   r_cols = (const int*)  d_in[6];
    const float* r_vals = (const float*)d_in[7];
    float* out = (float*)d_out;

    lgcn_zero<<<(N_CNT + 255) / 256, 256>>>();
    lgcn_hist<<<(NNZ_E + 255) / 256, 256>>>(a_rows, r_rows);
    lgcn_scan<<<2, 1024>>>();
    lgcn_scatter<<<(NNZ_E + 255) / 256, 256>>>(a_rows, a_cols, a_vals,
                                               r_rows, r_cols, r_vals);
    lgcn_gather<<<(N_CNT * 16 + 255) / 256, 256>>>(ue, ie, out);
}

// round 3
// speedup vs baseline: 2.3319x; 2.3319x over previous
#include <cuda_runtime.h>
#include <cstdint>

#define U_CNT 100000
#define I_CNT 50000
#define DIM   64
#define N_CNT 150000
#define NNZ_E 1000000

#define SCAN_B 1024
#define NBLK   ((N_CNT + SCAN_B - 1) / SCAN_B)   // 147

// ---- static device scratch (no runtime allocation) ----
__device__ int  g_rowptr_a[N_CNT + 1];
__device__ int  g_rowptr_r[N_CNT + 1];
__device__ int  g_cursor_a[N_CNT];
__device__ int  g_cursor_r[N_CNT];
__device__ int  g_part_a[NBLK];
__device__ int  g_part_r[NBLK];
__device__ int2 g_sorted_a[NNZ_E];    // (col, val bits) grouped by row
__device__ int2 g_sorted_r[NNZ_E];

static __device__ __forceinline__ const float4* ego_row(
    const float* __restrict__ ue, const float* __restrict__ ie, int n) {
    return (n < U_CNT)
        ? reinterpret_cast<const float4*>(ue + (size_t)n * DIM)
        : reinterpret_cast<const float4*>(ie + (size_t)(n - U_CNT) * DIM);
}

static __device__ __forceinline__ void fma4(float4& acc, float v, const float4& x) {
    acc.x = fmaf(v, x.x, acc.x);
    acc.y = fmaf(v, x.y, acc.y);
    acc.z = fmaf(v, x.z, acc.z);
    acc.w = fmaf(v, x.w, acc.w);
}

// K0: zero per-row counters (each graph replay must start clean).
__global__ void lgcn_zero() {
    int i = blockIdx.x * blockDim.x + threadIdx.x;
    if (i < N_CNT) { g_rowptr_a[i] = 0; g_rowptr_r[i] = 0; }
}

// K1: row histogram for both matrices.
__global__ void lgcn_hist(const int* __restrict__ a_rows,
                          const int* __restrict__ r_rows) {
    int i = blockIdx.x * blockDim.x + threadIdx.x;
    if (i < NNZ_E) {
        atomicAdd(&g_rowptr_a[__ldg(&a_rows[i])], 1);
        atomicAdd(&g_rowptr_r[__ldg(&r_rows[i])], 1);
    }
}

// K2a: per-block exclusive scan; emit block totals. grid = (NBLK, 2).
__global__ void lgcn_scan1() {
    int* cnt  = blockIdx.y ? g_rowptr_r : g_rowptr_a;
    int* part = blockIdx.y ? g_part_r   : g_part_a;
    int t = threadIdx.x;
    int i = blockIdx.x * SCAN_B + t;
    int v = (i < N_CNT) ? cnt[i] : 0;
    __shared__ int s[SCAN_B];
    s[t] = v;
    __syncthreads();
    for (int off = 1; off < SCAN_B; off <<= 1) {
        int u = (t >= off) ? s[t - off] : 0;
        __syncthreads();
        s[t] += u;
        __syncthreads();
    }
    if (i < N_CNT) cnt[i] = s[t] - v;                 // exclusive within block
    if (t == SCAN_B - 1) part[blockIdx.x] = s[t];     // block total
}

// K2b: scan the 147 block totals (both matrices in one block).
__global__ void lgcn_scan2() {
    __shared__ int sa[256], sr[256];
    int t = threadIdx.x;
    int va = (t < NBLK) ? g_part_a[t] : 0;
    int vr = (t < NBLK) ? g_part_r[t] : 0;
    sa[t] = va; sr[t] = vr;
    __syncthreads();
    for (int off = 1; off < 256; off <<= 1) {
        int ua = (t >= off) ? sa[t - off] : 0;
        int ur = (t >= off) ? sr[t - off] : 0;
        __syncthreads();
        sa[t] += ua; sr[t] += ur;
        __syncthreads();
    }
    if (t < NBLK) { g_part_a[t] = sa[t] - va; g_part_r[t] = sr[t] - vr; }
    if (t == 0) { g_rowptr_a[N_CNT] = NNZ_E; g_rowptr_r[N_CNT] = NNZ_E; }
}

// K2c: add block offsets; initialize scatter cursors. grid = (NBLK, 2).
__global__ void lgcn_scan3() {
    int* cnt  = blockIdx.y ? g_rowptr_r : g_rowptr_a;
    int* cur  = blockIdx.y ? g_cursor_r : g_cursor_a;
    const int* part = blockIdx.y ? g_part_r : g_part_a;
    int i = blockIdx.x * SCAN_B + threadIdx.x;
    if (i < N_CNT) {
        int v = cnt[i] + part[blockIdx.x];
        cnt[i] = v;
        cur[i] = v;
    }
}

// K3: scatter (col, val) into row-grouped order.
__global__ void lgcn_scatter(const int*  __restrict__ a_rows,
                             const int*  __restrict__ a_cols,
                             const float* __restrict__ a_vals,
                             const int*  __restrict__ r_rows,
                             const int*  __restrict__ r_cols,
                             const float* __restrict__ r_vals) {
    int i = blockIdx.x * blockDim.x + threadIdx.x;
    if (i >= NNZ_E) return;
    {
        int pos = atomicAdd(&g_cursor_a[__ldg(&a_rows[i])], 1);
        g_sorted_a[pos] = make_int2(__ldg(&a_cols[i]), __float_as_int(__ldg(&a_vals[i])));
    }
    {
        int pos = atomicAdd(&g_cursor_r[__ldg(&r_rows[i])], 1);
        g_sorted_r[pos] = make_int2(__ldg(&r_cols[i]), __float_as_int(__ldg(&r_vals[i])));
    }
}

// Unroll-4 CSR row reduction: 4 independent edge loads, then 4 independent gathers.
static __device__ __forceinline__ float4 row_reduce(
    const int2* __restrict__ sorted, int s, int e, int q,
    const float* __restrict__ ue, const float* __restrict__ ie) {
    float4 acc = make_float4(0.f, 0.f, 0.f, 0.f);
    int i = s;
    for (; i + 4 <= e; i += 4) {
        int2 c0 = __ldg(&sorted[i]);
        int2 c1 = __ldg(&sorted[i + 1]);
        int2 c2 = __ldg(&sorted[i + 2]);
        int2 c3 = __ldg(&sorted[i + 3]);
        float4 x0 = __ldg(&ego_row(ue, ie, c0.x)[q]);
        float4 x1 = __ldg(&ego_row(ue, ie, c1.x)[q]);
        float4 x2 = __ldg(&ego_row(ue, ie, c2.x)[q]);
        float4 x3 = __ldg(&ego_row(ue, ie, c3.x)[q]);
        fma4(acc, __int_as_float(c0.y), x0);
        fma4(acc, __int_as_float(c1.y), x1);
        fma4(acc, __int_as_float(c2.y), x2);
        fma4(acc, __int_as_float(c3.y), x3);
    }
    if (i < e) {
        // remainder 1..3: still batch the loads
        int2 c0 = __ldg(&sorted[i]);
        int2 c1 = (i + 1 < e) ? __ldg(&sorted[i + 1]) : make_int2(0, 0);
        int2 c2 = (i + 2 < e) ? __ldg(&sorted[i + 2]) : make_int2(0, 0);
        float4 x0 = __ldg(&ego_row(ue, ie, c0.x)[q]);
        fma4(acc, __int_as_float(c0.y), x0);
        if (i + 1 < e) {
            float4 x1 = __ldg(&ego_row(ue, ie, c1.x)[q]);
            fma4(acc, __int_as_float(c1.y), x1);
        }
        if (i + 2 < e) {
            float4 x2 = __ldg(&ego_row(ue, ie, c2.x)[q]);
            fma4(acc, __int_as_float(c2.y), x2);
        }
    }
    return acc;
}

// K4: per-row gather SpMM for both matrices + full output emit. No atomics.
__global__ void lgcn_gather(const float* __restrict__ ue,
                            const float* __restrict__ ie,
                            float* __restrict__ out) {
    int idx = blockIdx.x * blockDim.x + threadIdx.x;
    if (idx >= N_CNT * 16) return;
    int n = idx >> 4;
    int q = idx & 15;

    float4 e = __ldg(&ego_row(ue, ie, n)[q]);

    int s0 = __ldg(&g_rowptr_a[n]);
    int e0 = __ldg(&g_rowptr_a[n + 1]);
    float4 a = row_reduce(g_sorted_a, s0, e0, q, ue, ie);

    int s1 = __ldg(&g_rowptr_r[n]);
    int e1 = __ldg(&g_rowptr_r[n + 1]);
    float4 r = row_reduce(g_sorted_r, s1, e1, q, ue, ie);

    size_t sbase = (size_t)N_CNT * DIM + (size_t)n * 4 * DIM;
    size_t pbase = sbase + (size_t)N_CNT * 4 * DIM;
    float4* s = reinterpret_cast<float4*>(out + sbase);
    float4* p = reinterpret_cast<float4*>(out + pbase);
    s[q]      = e;        // stacked slot 0
    s[16 + q] = a;        // slots 1..3 identical (reference never updates ego)
    s[32 + q] = a;
    s[48 + q] = a;
    p[q]      = e;
    p[16 + q] = r;
    p[32 + q] = r;
    p[48 + q] = r;

    float4 m = make_float4((e.x + 3.f * a.x) * 0.25f,
                           (e.y + 3.f * a.y) * 0.25f,
                           (e.z + 3.f * a.z) * 0.25f,
                           (e.w + 3.f * a.w) * 0.25f);
    reinterpret_cast<float4*>(out)[(size_t)n * 16 + q] = m;
}

extern "C" void kernel_launch(void* const* d_in, const int* in_sizes, int n_in,
                              void* d_out, int out_size) {
    const float* ue     = (const float*)d_in[0];
    const float* ie     = (const float*)d_in[1];
    const int*   a_rows = (const int*)  d_in[2];
    const int*   a_cols = (const int*)  d_in[3];
    const float* a_vals = (const float*)d_in[4];
    const int*   r_rows = (const int*)  d_in[5];
    const int*   r_cols = (const int*)  d_in[6];
    const float* r_vals = (const float*)d_in[7];
    float* out = (float*)d_out;

    lgcn_zero<<<(N_CNT + 255) / 256, 256>>>();
    lgcn_hist<<<(NNZ_E + 255) / 256, 256>>>(a_rows, r_rows);
    lgcn_scan1<<<dim3(NBLK, 2), SCAN_B>>>();
    lgcn_scan2<<<1, 256>>>();
    lgcn_scan3<<<dim3(NBLK, 2), SCAN_B>>>();
    lgcn_scatter<<<(NNZ_E + 255) / 256, 256>>>(a_rows, a_cols, a_vals,
                                               r_rows, r_cols, r_vals);
    lgcn_gather<<<(N_CNT * 16 + 255) / 256, 256>>>(ue, ie, out);
}

// round 4
// speedup vs baseline: 2.3693x; 1.0160x over previous
#include <cuda_runtime.h>
#include <cstdint>

#define U_CNT 100000
#define I_CNT 50000
#define DIM   64
#define N_CNT 150000
#define NNZ_E 1000000

#define SCAN_B 1024
#define NBLK   ((N_CNT + SCAN_B - 1) / SCAN_B)   // 147

// ---- static device scratch (no runtime allocation) ----
__device__ int  g_rowptr_a[N_CNT + 1];
__device__ int  g_rowptr_r[N_CNT + 1];
__device__ int  g_cursor_a[N_CNT];
__device__ int  g_cursor_r[N_CNT];
__device__ unsigned int g_tile_a[NBLK];   // decoupled-lookback state: (value<<2)|status
__device__ unsigned int g_tile_r[NBLK];   // status: 0 invalid, 1 aggregate, 2 prefix
__device__ int2 g_sorted_a[NNZ_E];        // (col, val bits) grouped by row
__device__ int2 g_sorted_r[NNZ_E];

static __device__ __forceinline__ const float4* ego_row(
    const float* __restrict__ ue, const float* __restrict__ ie, int n) {
    return (n < U_CNT)
        ? reinterpret_cast<const float4*>(ue + (size_t)n * DIM)
        : reinterpret_cast<const float4*>(ie + (size_t)(n - U_CNT) * DIM);
}

static __device__ __forceinline__ void fma4(float4& acc, float v, const float4& x) {
    acc.x = fmaf(v, x.x, acc.x);
    acc.y = fmaf(v, x.y, acc.y);
    acc.z = fmaf(v, x.z, acc.z);
    acc.w = fmaf(v, x.w, acc.w);
}

// K0: zero counters + lookback state (each graph replay must start clean).
__global__ void lgcn_zero() {
    int i = blockIdx.x * blockDim.x + threadIdx.x;
    if (i < N_CNT) { g_rowptr_a[i] = 0; g_rowptr_r[i] = 0; }
    if (i < NBLK)  { g_tile_a[i] = 0u;  g_tile_r[i] = 0u; }
}

// K1: row histogram for both matrices.
__global__ void lgcn_hist(const int* __restrict__ a_rows,
                          const int* __restrict__ r_rows) {
    int i = blockIdx.x * blockDim.x + threadIdx.x;
    if (i < NNZ_E) {
        atomicAdd(&g_rowptr_a[__ldg(&a_rows[i])], 1);
        atomicAdd(&g_rowptr_r[__ldg(&r_rows[i])], 1);
    }
}

// K2: single-pass exclusive scan with decoupled lookback. grid = (NBLK, 2).
__global__ void lgcn_scan() {
    int  m = blockIdx.y;
    int  b = blockIdx.x;
    int  t = threadIdx.x;
    int* cnt = m ? g_rowptr_r : g_rowptr_a;
    int* cur = m ? g_cursor_r : g_cursor_a;
    unsigned int* st = m ? g_tile_r : g_tile_a;

    __shared__ int s[SCAN_B];
    __shared__ int ex_prefix;

    int i = b * SCAN_B + t;
    int v = (i < N_CNT) ? cnt[i] : 0;
    s[t] = v;
    __syncthreads();
    #pragma unroll
    for (int off = 1; off < SCAN_B; off <<= 1) {
        int u = (t >= off) ? s[t - off] : 0;
        __syncthreads();
        s[t] += u;
        __syncthreads();
    }
    int incl  = s[t];
    int total = s[SCAN_B - 1];

    if (t == 0) {
        if (b == 0) {
            ex_prefix = 0;
            atomicExch(&st[0], ((unsigned int)total << 2) | 2u);
        } else {
            atomicExch(&st[b], ((unsigned int)total << 2) | 1u);
            int run = 0;
            for (int j = b - 1; j >= 0; j--) {
                unsigned int x;
                do { x = atomicAdd(&st[j], 0u); } while ((x & 3u) == 0u);
                run += (int)(x >> 2);
                if ((x & 3u) == 2u) break;
            }
            ex_prefix = run;
            atomicExch(&st[b], ((unsigned int)(run + total) << 2) | 2u);
        }
    }
    __syncthreads();

    if (i < N_CNT) {
        int val = ex_prefix + incl - v;   // global exclusive prefix
        cnt[i] = val;
        cur[i] = val;
    }
    if (b == NBLK - 1 && t == SCAN_B - 1) cnt[N_CNT] = NNZ_E;
}

// K3: scatter (col, val) into row-grouped order. 4 edges/thread/matrix for MLP.
__global__ void lgcn_scatter(const int*  __restrict__ a_rows,
                             const int*  __restrict__ a_cols,
                             const float* __restrict__ a_vals,
                             const int*  __restrict__ r_rows,
                             const int*  __restrict__ r_cols,
                             const float* __restrict__ r_vals) {
    int i = blockIdx.x * blockDim.x + threadIdx.x;     // over NNZ/4
    if (i >= NNZ_E / 4) return;
    {
        int4   rw = __ldg((const int4*)a_rows + i);
        int4   cl = __ldg((const int4*)a_cols + i);
        float4 vl = __ldg((const float4*)a_vals + i);
        int p0 = atomicAdd(&g_cursor_a[rw.x], 1);
        int p1 = atomicAdd(&g_cursor_a[rw.y], 1);
        int p2 = atomicAdd(&g_cursor_a[rw.z], 1);
        int p3 = atomicAdd(&g_cursor_a[rw.w], 1);
        g_sorted_a[p0] = make_int2(cl.x, __float_as_int(vl.x));
        g_sorted_a[p1] = make_int2(cl.y, __float_as_int(vl.y));
        g_sorted_a[p2] = make_int2(cl.z, __float_as_int(vl.z));
        g_sorted_a[p3] = make_int2(cl.w, __float_as_int(vl.w));
    }
    {
        int4   rw = __ldg((const int4*)r_rows + i);
        int4   cl = __ldg((const int4*)r_cols + i);
        float4 vl = __ldg((const float4*)r_vals + i);
        int p0 = atomicAdd(&g_cursor_r[rw.x], 1);
        int p1 = atomicAdd(&g_cursor_r[rw.y], 1);
        int p2 = atomicAdd(&g_cursor_r[rw.z], 1);
        int p3 = atomicAdd(&g_cursor_r[rw.w], 1);
        g_sorted_r[p0] = make_int2(cl.x, __float_as_int(vl.x));
        g_sorted_r[p1] = make_int2(cl.y, __float_as_int(vl.y));
        g_sorted_r[p2] = make_int2(cl.z, __float_as_int(vl.z));
        g_sorted_r[p3] = make_int2(cl.w, __float_as_int(vl.w));
    }
}

// Unroll-4 CSR row reduction with batched independent loads.
static __device__ __forceinline__ float4 row_reduce(
    const int2* __restrict__ sorted, int s, int e, int q,
    const float* __restrict__ ue, const float* __restrict__ ie) {
    float4 acc = make_float4(0.f, 0.f, 0.f, 0.f);
    int i = s;
    for (; i + 4 <= e; i += 4) {
        int2 c0 = __ldg(&sorted[i]);
        int2 c1 = __ldg(&sorted[i + 1]);
        int2 c2 = __ldg(&sorted[i + 2]);
        int2 c3 = __ldg(&sorted[i + 3]);
        float4 x0 = __ldg(&ego_row(ue, ie, c0.x)[q]);
        float4 x1 = __ldg(&ego_row(ue, ie, c1.x)[q]);
        float4 x2 = __ldg(&ego_row(ue, ie, c2.x)[q]);
        float4 x3 = __ldg(&ego_row(ue, ie, c3.x)[q]);
        fma4(acc, __int_as_float(c0.y), x0);
        fma4(acc, __int_as_float(c1.y), x1);
        fma4(acc, __int_as_float(c2.y), x2);
        fma4(acc, __int_as_float(c3.y), x3);
    }
    if (i < e) {
        int2 c0 = __ldg(&sorted[i]);
        int2 c1 = (i + 1 < e) ? __ldg(&sorted[i + 1]) : make_int2(0, 0);
        int2 c2 = (i + 2 < e) ? __ldg(&sorted[i + 2]) : make_int2(0, 0);
        float4 x0 = __ldg(&ego_row(ue, ie, c0.x)[q]);
        fma4(acc, __int_as_float(c0.y), x0);
        if (i + 1 < e) {
            float4 x1 = __ldg(&ego_row(ue, ie, c1.x)[q]);
            fma4(acc, __int_as_float(c1.y), x1);
        }
        if (i + 2 < e) {
            float4 x2 = __ldg(&ego_row(ue, ie, c2.x)[q]);
            fma4(acc, __int_as_float(c2.y), x2);
        }
    }
    return acc;
}

// K4: per-row gather SpMM + full output emit. Streaming stores (never re-read).
__global__ void lgcn_gather(const float* __restrict__ ue,
                            const float* __restrict__ ie,
                            float* __restrict__ out) {
    int idx = blockIdx.x * blockDim.x + threadIdx.x;
    if (idx >= N_CNT * 16) return;
    int n = idx >> 4;
    int q = idx & 15;

    float4 e = __ldg(&ego_row(ue, ie, n)[q]);

    int s0 = __ldg(&g_rowptr_a[n]);
    int e0 = __ldg(&g_rowptr_a[n + 1]);
    float4 a = row_reduce(g_sorted_a, s0, e0, q, ue, ie);

    int s1 = __ldg(&g_rowptr_r[n]);
    int e1 = __ldg(&g_rowptr_r[n + 1]);
    float4 r = row_reduce(g_sorted_r, s1, e1, q, ue, ie);

    size_t sbase = (size_t)N_CNT * DIM + (size_t)n * 4 * DIM;
    size_t pbase = sbase + (size_t)N_CNT * 4 * DIM;
    float4* s = reinterpret_cast<float4*>(out + sbase);
    float4* p = reinterpret_cast<float4*>(out + pbase);
    __stcs(&s[q],      e);    // stacked slot 0
    __stcs(&s[16 + q], a);    // slots 1..3 identical (reference never updates ego)
    __stcs(&s[32 + q], a);
    __stcs(&s[48 + q], a);
    __stcs(&p[q],      e);
    __stcs(&p[16 + q], r);
    __stcs(&p[32 + q], r);
    __stcs(&p[48 + q], r);

    float4 m = make_float4((e.x + 3.f * a.x) * 0.25f,
                           (e.y + 3.f * a.y) * 0.25f,
                           (e.z + 3.f * a.z) * 0.25f,
                           (e.w + 3.f * a.w) * 0.25f);
    __stcs(&reinterpret_cast<float4*>(out)[(size_t)n * 16 + q], m);
}

extern "C" void kernel_launch(void* const* d_in, const int* in_sizes, int n_in,
                              void* d_out, int out_size) {
    const float* ue     = (const float*)d_in[0];
    const float* ie     = (const float*)d_in[1];
    const int*   a_rows = (const int*)  d_in[2];
    const int*   a_cols = (const int*)  d_in[3];
    const float* a_vals = (const float*)d_in[4];
    const int*   r_rows = (const int*)  d_in[5];
    const int*   r_cols = (const int*)  d_in[6];
    const float* r_vals = (const float*)d_in[7];
    float* out = (float*)d_out;

    lgcn_zero<<<(N_CNT + 255) / 256, 256>>>();
    lgcn_hist<<<(NNZ_E + 255) / 256, 256>>>(a_rows, r_rows);
    lgcn_scan<<<dim3(NBLK, 2), SCAN_B>>>();
    lgcn_scatter<<<(NNZ_E / 4 + 255) / 256, 256>>>(a_rows, a_cols, a_vals,
                                                   r_rows, r_cols, r_vals);
    lgcn_gather<<<(N_CNT * 16 + 255) / 256, 256>>>(ue, ie, out);
}